// round 15
// baseline (speedup 1.0000x reference)
#include <cuda_runtime.h>

#define B_     2
#define NPART  512
#define BN     1024
#define GBINS  48
#define TWO_PI 6.283185307179586f
#define INV_2PI 0.15915494309189535f

// ---------------- static device scratch ----------------
__device__ float    g_p1[BN * 2];
__device__ float    g_regC[BN * 128];
__device__ float    g_regD[BN * 128];
__device__ float4   g_ent[BN * 1024];         // 2 entries/neighbor: (cr0, cr1, cr2, j)
__device__ int      g_binStart[BN * 17];      // CSR over 16 t-columns
__device__ float    g_F[BN * GBINS * 128];
__device__ float    g_out[BN * 128];
__device__ float    g_actA[BN * 128];
__device__ float    g_actB[BN * 128];
__device__ float    g_Wbig[1253376];
__device__ float    g_WdT[26112];
__device__ float    g_part[16 * BN * 64];     // split-K partials (1M floats)
__constant__ int c_wOff[6] = {0, 196608, 393216, 786432, 1179648, 1253376};
__constant__ int c_dOff[6] = {0, 4096, 8192, 16384, 24576, 26112};

// ---------------- f32x2 helpers ----------------
__device__ __forceinline__ unsigned long long pack2(float x) {
    unsigned long long r;
    asm("mov.b64 %0, {%1, %1};" : "=l"(r) : "f"(x));
    return r;
}
__device__ __forceinline__ unsigned long long ffma2(unsigned long long a,
                                                    unsigned long long b,
                                                    unsigned long long c) {
    unsigned long long d;
    asm("fma.rn.f32x2 %0, %1, %2, %3;" : "=l"(d) : "l"(a), "l"(b), "l"(c));
    return d;
}
union F4U { float4 f4; float f[4]; unsigned long long u2[2]; };
union F2U { float2 f2; unsigned long long u2; };

// ---------------- prep: geom+lift (blocks 0..BN-1) and expand (rest) ----------------
__global__ void __launch_bounds__(256) prep_kernel(
        const float* __restrict__ mask, const float* __restrict__ p0,
        const float* __restrict__ v0, const float* __restrict__ a,
        const float* __restrict__ p0_enc, const float* __restrict__ v0_enc,
        const float* __restrict__ lc, const float* __restrict__ ld,
        const float* __restrict__ Wc0, const float* __restrict__ Wc1,
        const float* __restrict__ Wc2, const float* __restrict__ Wc3,
        const float* __restrict__ Wc4,
        const float* __restrict__ Wd0, const float* __restrict__ Wd1,
        const float* __restrict__ Wd2, const float* __restrict__ Wd3,
        const float* __restrict__ Wd4) {
    int tid = threadIdx.x;
    if (blockIdx.x >= BN) {
        const int Cs[5] = {16, 8, 8, 16, 8};
        const int Os[5] = {4, 8, 16, 8, 3};
        int idx = (blockIdx.x - BN) * 256 + tid;
        if (idx < 1253376) {
            int l = 0;
            while (idx >= c_wOff[l + 1]) ++l;
            int loc = idx - c_wOff[l];
            const float* Wc = (l == 0) ? Wc0 : (l == 1) ? Wc1 : (l == 2) ? Wc2 : (l == 3) ? Wc3 : Wc4;
            int C = Cs[l], OK = Os[l] * 8;
            int om = loc % OK;
            int kk = loc / OK;
            int n = kk & 7;
            int c = (kk >> 3) % C;
            int g = (kk >> 3) / C;
            int r = g >> 4, t = g & 15;
            int o = om >> 3, m = om & 7;
            g_Wbig[idx] = Wc[(((o * C + c) * 8 + ((n - m) & 7)) * 3 + r) * 16 + ((t - 2 * m) & 15)];
        } else if (idx < 1253376 + 26112) {
            int id2 = idx - 1253376;
            int l = 0;
            while (id2 >= c_dOff[l + 1]) ++l;
            int loc = id2 - c_dOff[l];
            const float* Wd = (l == 0) ? Wd0 : (l == 1) ? Wd1 : (l == 2) ? Wd2 : (l == 3) ? Wd3 : Wd4;
            int C = Cs[l], OK = Os[l] * 8;
            int om = loc % OK;
            int cn = loc / OK;
            int o = om >> 3, m = om & 7, c = cn >> 3, n = cn & 7;
            g_WdT[id2] = Wd[(o * C + c) * 8 + ((m - n) & 7)];
        }
        return;
    }

    __shared__ float sx[NPART], sy[NPART], smk[NPART], sw[NPART];
    __shared__ float red[256];
    __shared__ int cnt[16], offs[16], bstart[17];
    int bi = blockIdx.x;
    int b = bi >> 9, i = bi & 511;

    for (int j = tid; j < NPART; j += 256) {
        int gj = b * NPART + j;
        float vx = v0[gj * 2], vy = v0[gj * 2 + 1];
        sx[j] = p0[gj * 2 + 0] + vx + 0.5f * a[gj * 2 + 0];
        sy[j] = p0[gj * 2 + 1] + vy + 0.5f * a[gj * 2 + 1];
        smk[j] = mask[gj];
    }
    if (tid < 16) cnt[tid] = 0;

    if (tid < 128) {
        int c = tid >> 3, m = tid & 7;
        float v0x = v0[bi * 2 + 0], v0y = v0[bi * 2 + 1];
        float ax = a[bi * 2 + 0], ay = a[bi * 2 + 1];
        float v1x = v0x + ax, v1y = v0y + ay;
        float p1x = p0[bi * 2 + 0] + 0.5f * (v0x + v1x);
        float p1y = p0[bi * 2 + 1] + 0.5f * (v0y + v1y);
        float x, y;
        if (c == 0)      { x = v1x; y = v1y; }
        else if (c == 1) { x = p1x; y = p1y; }
        else if (c < 9)  { int t = c - 2; x = v0_enc[(bi * 7 + t) * 2 + 0]; y = v0_enc[(bi * 7 + t) * 2 + 1]; }
        else             { int t = c - 9; x = p0_enc[(bi * 7 + t) * 2 + 0]; y = p0_enc[(bi * 7 + t) * 2 + 1]; }
        float th = (float)m * 0.78539816339744831f;
        float cs = cosf(th), sn = sinf(th);
        float lc0 = lc[0], lc1 = lc[1], ld0 = ld[0], ld1 = ld[1];
        g_regC[bi * 128 + tid] = x * (lc0 * cs - lc1 * sn) + y * (lc0 * sn + lc1 * cs);
        g_regD[bi * 128 + tid] = x * (ld0 * cs - ld1 * sn) + y * (ld0 * sn + ld1 * cs);
    }
    __syncthreads();
    if (tid == 0) { g_p1[bi * 2] = sx[i]; g_p1[bi * 2 + 1] = sy[i]; }
    float xi = sx[i], yi = sy[i];

    float part = 0.f;
    for (int j = tid; j < NPART; j += 256) {
        float rx = sx[j] - xi, ry = sy[j] - yi;
        float d2 = (rx * rx + ry * ry + 1e-12f) * (0.025f * 0.025f);
        float u = fmaxf(1.f - d2, 0.f);
        float w = u * u * u * smk[j];
        sw[j] = w;
        part += w;
    }
    red[tid] = part;
    __syncthreads();
    for (int s = 128; s > 0; s >>= 1) { if (tid < s) red[tid] += red[tid + s]; __syncthreads(); }
    float inv = 1.f / (red[0] + 1e-6f);
    __syncthreads();

    float4 eloc[4];
    int tloc[4];
    int nloc = 0;
#pragma unroll
    for (int c = 0; c < 2; ++c) {
        int j = c * 256 + tid;
        float w = sw[j];
        if (w > 0.f) {
            float rx = sx[j] - xi, ry = sy[j] - yi;
            float d = sqrtf(rx * rx + ry * ry + 1e-12f) * 0.025f;
            float wb = w * inv;
            float rc = fminf(fmaxf(d * 3.f - 0.5f, 0.f), 2.f);
            float r0 = floorf(rc);
            float wr = rc - r0;
            int r0i = (int)r0;
            float w0 = wb * (1.f - wr), w1 = wb * wr;
            float b0, b1, b2;
            if (r0i == 0)      { b0 = w0; b1 = w1; b2 = 0.f; }
            else if (r0i == 1) { b0 = 0.f; b1 = w0; b2 = w1; }
            else               { b0 = 0.f; b1 = 0.f; b2 = w0 + w1; }
            float axv = (j == i) ? 1.f : rx;
            float ayv = (j == i) ? 0.f : ry;
            float ang = atan2f(ayv, axv);
            ang = ang - TWO_PI * floorf(ang * INV_2PI);
            float tc = ang * (16.f * INV_2PI);
            float t0 = floorf(tc);
            float wt = tc - t0;
            int t0i = ((int)t0) & 15;
            int t1i = (t0i + 1) & 15;
            float jf = __int_as_float(j);
            float u0 = 1.f - wt;
            eloc[nloc] = make_float4(b0 * u0, b1 * u0, b2 * u0, jf);
            tloc[nloc] = t0i;
            ++nloc;
            atomicAdd(&cnt[t0i], 1);
            eloc[nloc] = make_float4(b0 * wt, b1 * wt, b2 * wt, jf);
            tloc[nloc] = t1i;
            ++nloc;
            atomicAdd(&cnt[t1i], 1);
        }
    }
    __syncthreads();
    if (tid == 0) {
        int s = 0;
        for (int g = 0; g < 16; ++g) { bstart[g] = s; s += cnt[g]; }
        bstart[16] = s;
    }
    __syncthreads();
    if (tid < 16) offs[tid] = bstart[tid];
    if (tid < 17) g_binStart[bi * 17 + tid] = bstart[tid];
    __syncthreads();

    float4* ent = g_ent + (size_t)bi * 1024;
    for (int l = 0; l < nloc; ++l) {
        int pos = atomicAdd(&offs[tloc[l]], 1);
        ent[pos] = eloc[l];
    }
}

// ---------------- stage 1: t-column gather, warp-pair split + smem combine ----------------
// 1024 threads = 32 warps; warps 2c, 2c+1 split column c's list in half.
template <int CK>
__global__ void __launch_bounds__(1024) stage1_kernel(int srcsel) {
    const int V2 = CK / 64;
    __shared__ float smp[16 * 3 * CK];        // odd-half partials
    __shared__ int bs[17];
    int bi = blockIdx.x;
    int b = bi >> 9;
    int tid = threadIdx.x;
    int warp = tid >> 5, lane = tid & 31;
    int col = warp >> 1, half = warp & 1;
    const float* __restrict__ feats = (srcsel == 0) ? g_regC : (srcsel == 1) ? g_actA : g_actB;

    if (tid < 17) bs[tid] = g_binStart[bi * 17 + tid];
    __syncthreads();

    const float4* __restrict__ ent = g_ent + (size_t)bi * 1024;
    const float* __restrict__ fb = feats + (size_t)b * NPART * CK;

    unsigned long long a0[V2], a1[V2], a2[V2];
#pragma unroll
    for (int v = 0; v < V2; ++v) { a0[v] = 0ull; a1[v] = 0ull; a2[v] = 0ull; }

    int s0 = bs[col], e0 = bs[col + 1];
    int mid = s0 + ((e0 - s0) >> 1);
    int s = half ? mid : s0;
    int e = half ? e0 : mid;
    int k = s;
    if (V2 == 2) {
        for (; k + 2 <= e; k += 2) {
            float4 m0 = ent[k], m1 = ent[k + 1];
            int j0 = __float_as_int(m0.w), j1 = __float_as_int(m1.w);
            F4U f0, f1;
            f0.f4 = *(const float4*)(fb + j0 * CK + lane * 4);
            f1.f4 = *(const float4*)(fb + j1 * CK + lane * 4);
            unsigned long long p00 = pack2(m0.x), p01 = pack2(m0.y), p02 = pack2(m0.z);
            unsigned long long p10 = pack2(m1.x), p11 = pack2(m1.y), p12 = pack2(m1.z);
            a0[0] = ffma2(p00, f0.u2[0], a0[0]);
            a0[1] = ffma2(p00, f0.u2[1], a0[1]);
            a1[0] = ffma2(p01, f0.u2[0], a1[0]);
            a1[1] = ffma2(p01, f0.u2[1], a1[1]);
            a2[0] = ffma2(p02, f0.u2[0], a2[0]);
            a2[1] = ffma2(p02, f0.u2[1], a2[1]);
            a0[0] = ffma2(p10, f1.u2[0], a0[0]);
            a0[1] = ffma2(p10, f1.u2[1], a0[1]);
            a1[0] = ffma2(p11, f1.u2[0], a1[0]);
            a1[1] = ffma2(p11, f1.u2[1], a1[1]);
            a2[0] = ffma2(p12, f1.u2[0], a2[0]);
            a2[1] = ffma2(p12, f1.u2[1], a2[1]);
        }
        for (; k < e; ++k) {
            float4 m = ent[k];
            int j = __float_as_int(m.w);
            F4U f;
            f.f4 = *(const float4*)(fb + j * CK + lane * 4);
            unsigned long long p0 = pack2(m.x), p1 = pack2(m.y), p2 = pack2(m.z);
            a0[0] = ffma2(p0, f.u2[0], a0[0]);
            a0[1] = ffma2(p0, f.u2[1], a0[1]);
            a1[0] = ffma2(p1, f.u2[0], a1[0]);
            a1[1] = ffma2(p1, f.u2[1], a1[1]);
            a2[0] = ffma2(p2, f.u2[0], a2[0]);
            a2[1] = ffma2(p2, f.u2[1], a2[1]);
        }
    } else {
        for (; k + 4 <= e; k += 4) {
            float4 m0 = ent[k], m1 = ent[k + 1], m2 = ent[k + 2], m3 = ent[k + 3];
            F2U f0, f1, f2, f3;
            f0.f2 = *(const float2*)(fb + __float_as_int(m0.w) * CK + lane * 2);
            f1.f2 = *(const float2*)(fb + __float_as_int(m1.w) * CK + lane * 2);
            f2.f2 = *(const float2*)(fb + __float_as_int(m2.w) * CK + lane * 2);
            f3.f2 = *(const float2*)(fb + __float_as_int(m3.w) * CK + lane * 2);
            a0[0] = ffma2(pack2(m0.x), f0.u2, a0[0]);
            a1[0] = ffma2(pack2(m0.y), f0.u2, a1[0]);
            a2[0] = ffma2(pack2(m0.z), f0.u2, a2[0]);
            a0[0] = ffma2(pack2(m1.x), f1.u2, a0[0]);
            a1[0] = ffma2(pack2(m1.y), f1.u2, a1[0]);
            a2[0] = ffma2(pack2(m1.z), f1.u2, a2[0]);
            a0[0] = ffma2(pack2(m2.x), f2.u2, a0[0]);
            a1[0] = ffma2(pack2(m2.y), f2.u2, a1[0]);
            a2[0] = ffma2(pack2(m2.z), f2.u2, a2[0]);
            a0[0] = ffma2(pack2(m3.x), f3.u2, a0[0]);
            a1[0] = ffma2(pack2(m3.y), f3.u2, a1[0]);
            a2[0] = ffma2(pack2(m3.z), f3.u2, a2[0]);
        }
        for (; k < e; ++k) {
            float4 m = ent[k];
            F2U f;
            f.f2 = *(const float2*)(fb + __float_as_int(m.w) * CK + lane * 2);
            a0[0] = ffma2(pack2(m.x), f.u2, a0[0]);
            a1[0] = ffma2(pack2(m.y), f.u2, a1[0]);
            a2[0] = ffma2(pack2(m.z), f.u2, a2[0]);
        }
    }

    // odd half stores partials to smem; even half combines + writes g_F
    float* sp = smp + col * 3 * CK;
    if (half == 1) {
        if (V2 == 2) {
            F4U o0, o1, o2;
            o0.u2[0] = a0[0]; o0.u2[1] = a0[1];
            o1.u2[0] = a1[0]; o1.u2[1] = a1[1];
            o2.u2[0] = a2[0]; o2.u2[1] = a2[1];
            *(float4*)(sp + 0 * CK + lane * 4) = o0.f4;
            *(float4*)(sp + 1 * CK + lane * 4) = o1.f4;
            *(float4*)(sp + 2 * CK + lane * 4) = o2.f4;
        } else {
            F2U o0, o1, o2;
            o0.u2 = a0[0]; o1.u2 = a1[0]; o2.u2 = a2[0];
            *(float2*)(sp + 0 * CK + lane * 2) = o0.f2;
            *(float2*)(sp + 1 * CK + lane * 2) = o1.f2;
            *(float2*)(sp + 2 * CK + lane * 2) = o2.f2;
        }
    }
    __syncthreads();
    if (half == 0) {
        float* Fb = g_F + (size_t)bi * GBINS * CK;
        if (V2 == 2) {
            F4U o0, o1, o2;
            o0.u2[0] = a0[0]; o0.u2[1] = a0[1];
            o1.u2[0] = a1[0]; o1.u2[1] = a1[1];
            o2.u2[0] = a2[0]; o2.u2[1] = a2[1];
            float4 q0 = *(float4*)(sp + 0 * CK + lane * 4);
            float4 q1 = *(float4*)(sp + 1 * CK + lane * 4);
            float4 q2 = *(float4*)(sp + 2 * CK + lane * 4);
            o0.f4.x += q0.x; o0.f4.y += q0.y; o0.f4.z += q0.z; o0.f4.w += q0.w;
            o1.f4.x += q1.x; o1.f4.y += q1.y; o1.f4.z += q1.z; o1.f4.w += q1.w;
            o2.f4.x += q2.x; o2.f4.y += q2.y; o2.f4.z += q2.z; o2.f4.w += q2.w;
            *(float4*)(Fb + (0 * 16 + col) * CK + lane * 4) = o0.f4;
            *(float4*)(Fb + (1 * 16 + col) * CK + lane * 4) = o1.f4;
            *(float4*)(Fb + (2 * 16 + col) * CK + lane * 4) = o2.f4;
        } else {
            F2U o0, o1, o2;
            o0.u2 = a0[0]; o1.u2 = a1[0]; o2.u2 = a2[0];
            float2 q0 = *(float2*)(sp + 0 * CK + lane * 2);
            float2 q1 = *(float2*)(sp + 1 * CK + lane * 2);
            float2 q2 = *(float2*)(sp + 2 * CK + lane * 2);
            o0.f2.x += q0.x; o0.f2.y += q0.y;
            o1.f2.x += q1.x; o1.f2.y += q1.y;
            o2.f2.x += q2.x; o2.f2.y += q2.y;
            *(float2*)(Fb + (0 * 16 + col) * CK + lane * 2) = o0.f2;
            *(float2*)(Fb + (1 * 16 + col) * CK + lane * 2) = o1.f2;
            *(float2*)(Fb + (2 * 16 + col) * CK + lane * 2) = o2.f2;
        }
    }
}

// ---------------- stage 2a: split-K GEMM (partials only) ----------------
template <int OK, int TM, int ROWS, int CPT, int KS>
__global__ void __launch_bounds__((TM / ROWS) * (OK / CPT)) gemm_kernel(int KD, int wOff) {
    const int KB = 32;
    const int THREADS = (TM / ROWS) * (OK / CPT);
    const int NW4 = (KB * OK / 4 + THREADS - 1) / THREADS;
    const int NF4 = (TM * KB / 4 + THREADS - 1) / THREADS;
    __shared__ __align__(16) float Wt[KB * OK];
    __shared__ __align__(16) float Ft[TM * KB];
    int tid = threadIdx.x;
    int i0 = blockIdx.x * TM;
    int KC = KD / KS;
    int k0 = blockIdx.y * KC;
    int NCH = KC / KB;

    const float* Wsrc = g_Wbig + wOff + (size_t)k0 * OK;

    float4 wreg[NW4], freg[NF4];
    {
        const float4* src = (const float4*)Wsrc;
#pragma unroll
        for (int u = 0; u < NW4; ++u) {
            int x = tid + u * THREADS;
            if (x < KB * OK / 4) wreg[u] = src[x];
        }
#pragma unroll
        for (int u = 0; u < NF4; ++u) {
            int x = tid + u * THREADS;
            if (x < TM * KB / 4) {
                int row = x / (KB / 4), kc = x % (KB / 4);
                freg[u] = *(const float4*)(g_F + (size_t)(i0 + row) * KD + k0 + kc * 4);
            }
        }
    }

    int rg = tid / (OK / CPT);
    int cg = (tid % (OK / CPT)) * CPT;
    unsigned long long accp[ROWS][CPT / 2];
#pragma unroll
    for (int r = 0; r < ROWS; ++r)
#pragma unroll
        for (int c = 0; c < CPT / 2; ++c) accp[r][c] = 0ull;

    for (int ch = 0; ch < NCH; ++ch) {
        __syncthreads();
#pragma unroll
        for (int u = 0; u < NW4; ++u) {
            int x = tid + u * THREADS;
            if (x < KB * OK / 4) ((float4*)Wt)[x] = wreg[u];
        }
#pragma unroll
        for (int u = 0; u < NF4; ++u) {
            int x = tid + u * THREADS;
            if (x < TM * KB / 4) ((float4*)Ft)[x] = freg[u];
        }
        __syncthreads();
        if (ch + 1 < NCH) {
            const float4* src = (const float4*)(Wsrc + (size_t)(ch + 1) * KB * OK);
#pragma unroll
            for (int u = 0; u < NW4; ++u) {
                int x = tid + u * THREADS;
                if (x < KB * OK / 4) wreg[u] = src[x];
            }
#pragma unroll
            for (int u = 0; u < NF4; ++u) {
                int x = tid + u * THREADS;
                if (x < TM * KB / 4) {
                    int rr = x / (KB / 4), kc = x % (KB / 4);
                    freg[u] = *(const float4*)(g_F + (size_t)(i0 + rr) * KD + k0 + (ch + 1) * KB + kc * 4);
                }
            }
        }
#pragma unroll 4
        for (int k = 0; k < KB; ++k) {
            unsigned long long fp[ROWS];
#pragma unroll
            for (int r = 0; r < ROWS; ++r)
                fp[r] = pack2(Ft[(rg * ROWS + r) * KB + k]);
#pragma unroll
            for (int c = 0; c < CPT; c += 4) {
                F4U w;
                w.f4 = *(const float4*)&Wt[k * OK + cg + c];
#pragma unroll
                for (int r = 0; r < ROWS; ++r) {
                    accp[r][c / 2]     = ffma2(fp[r], w.u2[0], accp[r][c / 2]);
                    accp[r][c / 2 + 1] = ffma2(fp[r], w.u2[1], accp[r][c / 2 + 1]);
                }
            }
        }
    }

#pragma unroll
    for (int r = 0; r < ROWS; ++r) {
        float* dst = g_part + ((size_t)blockIdx.y * BN + i0 + rg * ROWS + r) * OK + cg;
#pragma unroll
        for (int c = 0; c < CPT; c += 4) {
            F4U o;
            o.u2[0] = accp[r][c / 2];
            o.u2[1] = accp[r][c / 2 + 1];
            *(float4*)&dst[c] = o.f4;
        }
    }
}

// ---------------- stage 2b: 4-way split-parallel reduce + dense + epilogue ----------------
template <int OK, int KS, int CK>
__global__ void __launch_bounds__(256) reduce_kernel(int mode, int dOff,
                                                     int ain, int aout) {
    int tid = threadIdx.x;
    int warp = tid >> 5, lane = tid & 31;
    int s = lane & 3;
    int gidx = blockIdx.x * 64 + warp * 8 + (lane >> 2);
    int bi = gidx / OK, om = gidx % OK;

    float oc = 0.f;
#pragma unroll
    for (int ks = s; ks < KS; ks += 4)
        oc += g_part[((size_t)ks * BN + bi) * OK + om];

    const float* __restrict__ densein = (ain == 0) ? g_regD : (ain == 1) ? g_actA : g_actB;
    float* __restrict__ actout = (aout == 1) ? g_actA : g_actB;
    const float* WdT = g_WdT + dOff;
    const float* x = densein + (size_t)bi * CK;
    float od = 0.f;
    const int CPT = CK / 4;
#pragma unroll
    for (int u = 0; u < CPT; ++u) {
        int cn = s * CPT + u;
        od = fmaf(x[cn], WdT[cn * OK + om], od);
    }
    oc += __shfl_xor_sync(0xffffffffu, oc, 1);
    oc += __shfl_xor_sync(0xffffffffu, oc, 2);
    od += __shfl_xor_sync(0xffffffffu, od, 1);
    od += __shfl_xor_sync(0xffffffffu, od, 2);

    if (mode == 0) {
        float sc = oc * oc;
        sc += __shfl_xor_sync(0xffffffffu, sc, 4);
        sc += __shfl_xor_sync(0xffffffffu, sc, 8);
        sc += __shfl_xor_sync(0xffffffffu, sc, 16);
        float mc = sc + 1e-6f;
        float sd = od * od;
        sd += __shfl_xor_sync(0xffffffffu, sd, 4);
        sd += __shfl_xor_sync(0xffffffffu, sd, 8);
        sd += __shfl_xor_sync(0xffffffffu, sd, 16);
        float md = sd + 1e-6f;
        if (s == 0) {
            g_out[bi * 64 + om] = oc;
            g_out[bi * 64 + 32 + om] = od;
            actout[bi * 64 + om] = oc / mc * fmaxf(mc - 0.2f, 0.f);
            actout[bi * 64 + 32 + om] = od / md * fmaxf(md - 0.2f, 0.f);
        }
    } else {
        float v = oc + od;
        if (mode == 2) v += g_out[bi * OK + om];
        float sq = v * v;
        sq += __shfl_xor_sync(0xffffffffu, sq, 4);
        sq += __shfl_xor_sync(0xffffffffu, sq, 8);
        sq += __shfl_xor_sync(0xffffffffu, sq, 16);
        float mg = sq + 1e-6f;
        if (s == 0) {
            g_out[bi * OK + om] = v;
            actout[bi * OK + om] = v / mg * fmaxf(mg - 0.2f, 0.f);
        }
    }
}

// ---------------- last layer: split-parallel reduce + dense + projection ----------------
__global__ void __launch_bounds__(256) reduce_last(const float* __restrict__ p0,
                                                   const float* __restrict__ pc,
                                                   const float* __restrict__ pd,
                                                   float* __restrict__ outp) {
    const int OK = 24, KS = 8, CK = 64;
    int tid = threadIdx.x;
    int warp = tid >> 5, lane = tid & 31;
    int s = lane & 3;
    int gidx = blockIdx.x * 64 + warp * 8 + (lane >> 2);
    int bi = gidx / OK, om = gidx % OK;
    int m = om & 7, ch = om >> 3;

    float oc = 0.f;
#pragma unroll
    for (int ks = s; ks < KS; ks += 4)
        oc += g_part[((size_t)ks * BN + bi) * OK + om];

    const float* WdT = g_WdT + 24576;
    const float* x = g_actB + (size_t)bi * CK;
    float od = 0.f;
#pragma unroll
    for (int u = 0; u < 16; ++u) {
        int cn = s * 16 + u;
        od = fmaf(x[cn], WdT[cn * OK + om], od);
    }
    oc += __shfl_xor_sync(0xffffffffu, oc, 1);
    oc += __shfl_xor_sync(0xffffffffu, oc, 2);
    od += __shfl_xor_sync(0xffffffffu, od, 1);
    od += __shfl_xor_sync(0xffffffffu, od, 2);

    float th = (float)m * 0.78539816339744831f;
    float cs = cosf(th), sn = sinf(th);
    float c0 = pc[0], c1 = pc[1], d0 = pd[0], d1 = pd[1];
    float resx = oc * (c0 * cs - c1 * sn) + od * (d0 * cs - d1 * sn);
    float resy = oc * (c0 * sn + c1 * cs) + od * (d0 * sn + d1 * cs);
    resx += __shfl_xor_sync(0xffffffffu, resx, 4);
    resx += __shfl_xor_sync(0xffffffffu, resx, 8);
    resx += __shfl_xor_sync(0xffffffffu, resx, 16);
    resy += __shfl_xor_sync(0xffffffffu, resy, 4);
    resy += __shfl_xor_sync(0xffffffffu, resy, 8);
    resy += __shfl_xor_sync(0xffffffffu, resy, 16);

    if (lane == 0) {
        const float CORR = 1.0f / 128.0f;
        resx *= CORR;
        resy *= CORR;
        if (ch == 0) {
            float px = g_p1[bi * 2 + 0] + resx;
            float py = g_p1[bi * 2 + 1] + resy;
            outp[bi * 2 + 0] = px;
            outp[bi * 2 + 1] = py;
            outp[BN * 2 + bi * 2 + 0] = px - p0[bi * 2 + 0];
            outp[BN * 2 + bi * 2 + 1] = py - p0[bi * 2 + 1];
        } else {
            outp[BN * 4 + bi * 4 + (ch - 1) * 2 + 0] = resx;
            outp[BN * 4 + bi * 4 + (ch - 1) * 2 + 1] = resy;
        }
    }
}

// ---------------- launch ----------------
extern "C" void kernel_launch(void* const* d_in, const int* in_sizes, int n_in,
                              void* d_out, int out_size) {
    const float* p0_enc  = (const float*)d_in[0];
    const float* v0_enc  = (const float*)d_in[1];
    const float* p0      = (const float*)d_in[2];
    const float* v0      = (const float*)d_in[3];
    const float* a       = (const float*)d_in[4];
    const float* mask    = (const float*)d_in[5];
    const float* lift_c0 = (const float*)d_in[6];
    const float* Wc0     = (const float*)d_in[7];
    const float* lift_d0 = (const float*)d_in[8];
    const float* Wd0     = (const float*)d_in[9];
    const float* Wc1     = (const float*)d_in[10];
    const float* Wd1     = (const float*)d_in[11];
    const float* Wc2     = (const float*)d_in[12];
    const float* Wd2     = (const float*)d_in[13];
    const float* Wc3     = (const float*)d_in[14];
    const float* Wd3     = (const float*)d_in[15];
    const float* Wc4     = (const float*)d_in[16];
    const float* proj_c4 = (const float*)d_in[17];
    const float* Wd4     = (const float*)d_in[18];
    const float* proj_d4 = (const float*)d_in[19];

    const int NEXP = (1253376 + 26112 + 255) / 256;
    prep_kernel<<<BN + NEXP, 256>>>(mask, p0, v0, a, p0_enc, v0_enc,
                                    lift_c0, lift_d0,
                                    Wc0, Wc1, Wc2, Wc3, Wc4,
                                    Wd0, Wd1, Wd2, Wd3, Wd4);

    const int wOff[5] = {0, 196608, 393216, 786432, 1179648};
    const int dOff[5] = {0, 4096, 8192, 16384, 24576};

    // act ping-pong: L0 -> A; L1: A->B; L2: B->A; L3: A->B; L4: reads B
    // L0: CK=128, OK=32, KD=6144
    stage1_kernel<128><<<BN, 1024>>>(0);
    gemm_kernel<32, 128, 2, 8, 16><<<dim3(8, 16), 256>>>(6144, wOff[0]);
    reduce_kernel<32, 16, 128><<<BN * 32 / 64, 256>>>(0, dOff[0], 0, 1);
    // L1: CK=64, OK=64, KD=3072, residual
    stage1_kernel<64><<<BN, 1024>>>(1);
    gemm_kernel<64, 64, 2, 8, 16><<<dim3(16, 16), 256>>>(3072, wOff[1]);
    reduce_kernel<64, 16, 64><<<BN * 64 / 64, 256>>>(2, dOff[1], 1, 2);
    // L2: CK=64, OK=128, KD=3072
    stage1_kernel<64><<<BN, 1024>>>(2);
    gemm_kernel<128, 32, 2, 8, 8><<<dim3(32, 8), 256>>>(3072, wOff[2]);
    reduce_kernel<128, 8, 64><<<BN * 128 / 64, 256>>>(1, dOff[2], 2, 1);
    // L3: CK=128, OK=64, KD=6144
    stage1_kernel<128><<<BN, 1024>>>(1);
    gemm_kernel<64, 64, 2, 8, 16><<<dim3(16, 16), 256>>>(6144, wOff[3]);
    reduce_kernel<64, 16, 128><<<BN * 64 / 64, 256>>>(1, dOff[3], 1, 2);
    // L4: CK=64, OK=24, KD=3072, last (fused projection)
    stage1_kernel<64><<<BN, 1024>>>(2);
    gemm_kernel<24, 128, 2, 8, 8><<<dim3(8, 8), 192>>>(3072, wOff[4]);
    reduce_last<<<BN * 24 / 64, 256>>>(p0, proj_c4, proj_d4, (float*)d_out);
}

// round 16
// speedup vs baseline: 1.0994x; 1.0994x over previous
#include <cuda_runtime.h>

#define B_     2
#define NPART  512
#define BN     1024
#define GBINS  48
#define TWO_PI 6.283185307179586f
#define INV_2PI 0.15915494309189535f

// ---------------- static device scratch ----------------
__device__ float    g_p1[BN * 2];
__device__ float    g_regC[BN * 128];
__device__ float    g_regD[BN * 128];
__device__ float4   g_ent[BN * 1024];         // 2 entries/neighbor: (cr0, cr1, cr2, j)
__device__ int      g_binStart[BN * 17];      // CSR over 16 t-columns
__device__ float    g_F[BN * GBINS * 128];
__device__ float    g_out[BN * 128];
__device__ float    g_actA[BN * 128];
__device__ float    g_actB[BN * 128];
__device__ float    g_Wbig[1253376];
__device__ float    g_WdT[26112];
__device__ float    g_part[16 * BN * 64];     // split-K partials (1M floats)
__constant__ int c_wOff[6] = {0, 196608, 393216, 786432, 1179648, 1253376};
__constant__ int c_dOff[6] = {0, 4096, 8192, 16384, 24576, 26112};

// ---------------- f32x2 helpers ----------------
__device__ __forceinline__ unsigned long long pack2(float x) {
    unsigned long long r;
    asm("mov.b64 %0, {%1, %1};" : "=l"(r) : "f"(x));
    return r;
}
__device__ __forceinline__ unsigned long long ffma2(unsigned long long a,
                                                    unsigned long long b,
                                                    unsigned long long c) {
    unsigned long long d;
    asm("fma.rn.f32x2 %0, %1, %2, %3;" : "=l"(d) : "l"(a), "l"(b), "l"(c));
    return d;
}
union F4U { float4 f4; float f[4]; unsigned long long u2[2]; };
union F2U { float2 f2; unsigned long long u2; };

// ---------------- prep: geom+lift (blocks 0..BN-1) and expand (rest) ----------------
__global__ void __launch_bounds__(256) prep_kernel(
        const float* __restrict__ mask, const float* __restrict__ p0,
        const float* __restrict__ v0, const float* __restrict__ a,
        const float* __restrict__ p0_enc, const float* __restrict__ v0_enc,
        const float* __restrict__ lc, const float* __restrict__ ld,
        const float* __restrict__ Wc0, const float* __restrict__ Wc1,
        const float* __restrict__ Wc2, const float* __restrict__ Wc3,
        const float* __restrict__ Wc4,
        const float* __restrict__ Wd0, const float* __restrict__ Wd1,
        const float* __restrict__ Wd2, const float* __restrict__ Wd3,
        const float* __restrict__ Wd4) {
    int tid = threadIdx.x;
    if (blockIdx.x >= BN) {
        const int Cs[5] = {16, 8, 8, 16, 8};
        const int Os[5] = {4, 8, 16, 8, 3};
        int idx = (blockIdx.x - BN) * 256 + tid;
        if (idx < 1253376) {
            int l = 0;
            while (idx >= c_wOff[l + 1]) ++l;
            int loc = idx - c_wOff[l];
            const float* Wc = (l == 0) ? Wc0 : (l == 1) ? Wc1 : (l == 2) ? Wc2 : (l == 3) ? Wc3 : Wc4;
            int C = Cs[l], OK = Os[l] * 8;
            int om = loc % OK;
            int kk = loc / OK;
            int n = kk & 7;
            int c = (kk >> 3) % C;
            int g = (kk >> 3) / C;
            int r = g >> 4, t = g & 15;
            int o = om >> 3, m = om & 7;
            g_Wbig[idx] = Wc[(((o * C + c) * 8 + ((n - m) & 7)) * 3 + r) * 16 + ((t - 2 * m) & 15)];
        } else if (idx < 1253376 + 26112) {
            int id2 = idx - 1253376;
            int l = 0;
            while (id2 >= c_dOff[l + 1]) ++l;
            int loc = id2 - c_dOff[l];
            const float* Wd = (l == 0) ? Wd0 : (l == 1) ? Wd1 : (l == 2) ? Wd2 : (l == 3) ? Wd3 : Wd4;
            int C = Cs[l], OK = Os[l] * 8;
            int om = loc % OK;
            int cn = loc / OK;
            int o = om >> 3, m = om & 7, c = cn >> 3, n = cn & 7;
            g_WdT[id2] = Wd[(o * C + c) * 8 + ((m - n) & 7)];
        }
        return;
    }

    __shared__ float sx[NPART], sy[NPART], smk[NPART], sw[NPART];
    __shared__ float red[256];
    __shared__ int cnt[16], offs[16], bstart[17];
    int bi = blockIdx.x;
    int b = bi >> 9, i = bi & 511;

    for (int j = tid; j < NPART; j += 256) {
        int gj = b * NPART + j;
        float vx = v0[gj * 2], vy = v0[gj * 2 + 1];
        sx[j] = p0[gj * 2 + 0] + vx + 0.5f * a[gj * 2 + 0];
        sy[j] = p0[gj * 2 + 1] + vy + 0.5f * a[gj * 2 + 1];
        smk[j] = mask[gj];
    }
    if (tid < 16) cnt[tid] = 0;

    if (tid < 128) {
        int c = tid >> 3, m = tid & 7;
        float v0x = v0[bi * 2 + 0], v0y = v0[bi * 2 + 1];
        float ax = a[bi * 2 + 0], ay = a[bi * 2 + 1];
        float v1x = v0x + ax, v1y = v0y + ay;
        float p1x = p0[bi * 2 + 0] + 0.5f * (v0x + v1x);
        float p1y = p0[bi * 2 + 1] + 0.5f * (v0y + v1y);
        float x, y;
        if (c == 0)      { x = v1x; y = v1y; }
        else if (c == 1) { x = p1x; y = p1y; }
        else if (c < 9)  { int t = c - 2; x = v0_enc[(bi * 7 + t) * 2 + 0]; y = v0_enc[(bi * 7 + t) * 2 + 1]; }
        else             { int t = c - 9; x = p0_enc[(bi * 7 + t) * 2 + 0]; y = p0_enc[(bi * 7 + t) * 2 + 1]; }
        float th = (float)m * 0.78539816339744831f;
        float cs = cosf(th), sn = sinf(th);
        float lc0 = lc[0], lc1 = lc[1], ld0 = ld[0], ld1 = ld[1];
        g_regC[bi * 128 + tid] = x * (lc0 * cs - lc1 * sn) + y * (lc0 * sn + lc1 * cs);
        g_regD[bi * 128 + tid] = x * (ld0 * cs - ld1 * sn) + y * (ld0 * sn + ld1 * cs);
    }
    __syncthreads();
    if (tid == 0) { g_p1[bi * 2] = sx[i]; g_p1[bi * 2 + 1] = sy[i]; }
    float xi = sx[i], yi = sy[i];

    float part = 0.f;
    for (int j = tid; j < NPART; j += 256) {
        float rx = sx[j] - xi, ry = sy[j] - yi;
        float d2 = (rx * rx + ry * ry + 1e-12f) * (0.025f * 0.025f);
        float u = fmaxf(1.f - d2, 0.f);
        float w = u * u * u * smk[j];
        sw[j] = w;
        part += w;
    }
    red[tid] = part;
    __syncthreads();
    for (int s = 128; s > 0; s >>= 1) { if (tid < s) red[tid] += red[tid + s]; __syncthreads(); }
    float inv = 1.f / (red[0] + 1e-6f);
    __syncthreads();

    float4 eloc[4];
    int tloc[4];
    int nloc = 0;
#pragma unroll
    for (int c = 0; c < 2; ++c) {
        int j = c * 256 + tid;
        float w = sw[j];
        if (w > 0.f) {
            float rx = sx[j] - xi, ry = sy[j] - yi;
            float d = sqrtf(rx * rx + ry * ry + 1e-12f) * 0.025f;
            float wb = w * inv;
            float rc = fminf(fmaxf(d * 3.f - 0.5f, 0.f), 2.f);
            float r0 = floorf(rc);
            float wr = rc - r0;
            int r0i = (int)r0;
            float w0 = wb * (1.f - wr), w1 = wb * wr;
            float b0, b1, b2;
            if (r0i == 0)      { b0 = w0; b1 = w1; b2 = 0.f; }
            else if (r0i == 1) { b0 = 0.f; b1 = w0; b2 = w1; }
            else               { b0 = 0.f; b1 = 0.f; b2 = w0 + w1; }
            float axv = (j == i) ? 1.f : rx;
            float ayv = (j == i) ? 0.f : ry;
            float ang = atan2f(ayv, axv);
            ang = ang - TWO_PI * floorf(ang * INV_2PI);
            float tc = ang * (16.f * INV_2PI);
            float t0 = floorf(tc);
            float wt = tc - t0;
            int t0i = ((int)t0) & 15;
            int t1i = (t0i + 1) & 15;
            float jf = __int_as_float(j);
            float u0 = 1.f - wt;
            eloc[nloc] = make_float4(b0 * u0, b1 * u0, b2 * u0, jf);
            tloc[nloc] = t0i;
            ++nloc;
            atomicAdd(&cnt[t0i], 1);
            eloc[nloc] = make_float4(b0 * wt, b1 * wt, b2 * wt, jf);
            tloc[nloc] = t1i;
            ++nloc;
            atomicAdd(&cnt[t1i], 1);
        }
    }
    __syncthreads();
    if (tid == 0) {
        int s = 0;
        for (int g = 0; g < 16; ++g) { bstart[g] = s; s += cnt[g]; }
        bstart[16] = s;
    }
    __syncthreads();
    if (tid < 16) offs[tid] = bstart[tid];
    if (tid < 17) g_binStart[bi * 17 + tid] = bstart[tid];
    __syncthreads();

    float4* ent = g_ent + (size_t)bi * 1024;
    for (int l = 0; l < nloc; ++l) {
        int pos = atomicAdd(&offs[tloc[l]], 1);
        ent[pos] = eloc[l];
    }
}

// ---------------- stage 1: t-column gather, 8 warps/block, grid 2*BN ----------------
template <int CK>
__global__ void __launch_bounds__(256) stage1_kernel(int srcsel) {
    const int V2 = CK / 64;
    int bi = blockIdx.x >> 1;
    int grp = blockIdx.x & 1;
    int b = bi >> 9;
    int tid = threadIdx.x;
    int warp = tid >> 5, lane = tid & 31;
    int col = grp * 8 + warp;
    const float* __restrict__ feats = (srcsel == 0) ? g_regC : (srcsel == 1) ? g_actA : g_actB;

    __shared__ int bs[17];
    if (tid < 17) bs[tid] = g_binStart[bi * 17 + tid];
    __syncthreads();

    const float4* __restrict__ ent = g_ent + (size_t)bi * 1024;
    const float* __restrict__ fb = feats + (size_t)b * NPART * CK;

    unsigned long long a0[V2], a1[V2], a2[V2];
#pragma unroll
    for (int v = 0; v < V2; ++v) { a0[v] = 0ull; a1[v] = 0ull; a2[v] = 0ull; }

    int s = bs[col], e = bs[col + 1];
    int k = s;
    if (V2 == 2) {
        for (; k + 2 <= e; k += 2) {
            float4 m0 = ent[k], m1 = ent[k + 1];
            int j0 = __float_as_int(m0.w), j1 = __float_as_int(m1.w);
            F4U f0, f1;
            f0.f4 = *(const float4*)(fb + j0 * CK + lane * 4);
            f1.f4 = *(const float4*)(fb + j1 * CK + lane * 4);
            unsigned long long p00 = pack2(m0.x), p01 = pack2(m0.y), p02 = pack2(m0.z);
            unsigned long long p10 = pack2(m1.x), p11 = pack2(m1.y), p12 = pack2(m1.z);
            a0[0] = ffma2(p00, f0.u2[0], a0[0]);
            a0[1] = ffma2(p00, f0.u2[1], a0[1]);
            a1[0] = ffma2(p01, f0.u2[0], a1[0]);
            a1[1] = ffma2(p01, f0.u2[1], a1[1]);
            a2[0] = ffma2(p02, f0.u2[0], a2[0]);
            a2[1] = ffma2(p02, f0.u2[1], a2[1]);
            a0[0] = ffma2(p10, f1.u2[0], a0[0]);
            a0[1] = ffma2(p10, f1.u2[1], a0[1]);
            a1[0] = ffma2(p11, f1.u2[0], a1[0]);
            a1[1] = ffma2(p11, f1.u2[1], a1[1]);
            a2[0] = ffma2(p12, f1.u2[0], a2[0]);
            a2[1] = ffma2(p12, f1.u2[1], a2[1]);
        }
        for (; k < e; ++k) {
            float4 m = ent[k];
            int j = __float_as_int(m.w);
            F4U f;
            f.f4 = *(const float4*)(fb + j * CK + lane * 4);
            unsigned long long p0 = pack2(m.x), p1 = pack2(m.y), p2 = pack2(m.z);
            a0[0] = ffma2(p0, f.u2[0], a0[0]);
            a0[1] = ffma2(p0, f.u2[1], a0[1]);
            a1[0] = ffma2(p1, f.u2[0], a1[0]);
            a1[1] = ffma2(p1, f.u2[1], a1[1]);
            a2[0] = ffma2(p2, f.u2[0], a2[0]);
            a2[1] = ffma2(p2, f.u2[1], a2[1]);
        }
    } else {
        for (; k + 4 <= e; k += 4) {
            float4 m0 = ent[k], m1 = ent[k + 1], m2 = ent[k + 2], m3 = ent[k + 3];
            F2U f0, f1, f2, f3;
            f0.f2 = *(const float2*)(fb + __float_as_int(m0.w) * CK + lane * 2);
            f1.f2 = *(const float2*)(fb + __float_as_int(m1.w) * CK + lane * 2);
            f2.f2 = *(const float2*)(fb + __float_as_int(m2.w) * CK + lane * 2);
            f3.f2 = *(const float2*)(fb + __float_as_int(m3.w) * CK + lane * 2);
            a0[0] = ffma2(pack2(m0.x), f0.u2, a0[0]);
            a1[0] = ffma2(pack2(m0.y), f0.u2, a1[0]);
            a2[0] = ffma2(pack2(m0.z), f0.u2, a2[0]);
            a0[0] = ffma2(pack2(m1.x), f1.u2, a0[0]);
            a1[0] = ffma2(pack2(m1.y), f1.u2, a1[0]);
            a2[0] = ffma2(pack2(m1.z), f1.u2, a2[0]);
            a0[0] = ffma2(pack2(m2.x), f2.u2, a0[0]);
            a1[0] = ffma2(pack2(m2.y), f2.u2, a1[0]);
            a2[0] = ffma2(pack2(m2.z), f2.u2, a2[0]);
            a0[0] = ffma2(pack2(m3.x), f3.u2, a0[0]);
            a1[0] = ffma2(pack2(m3.y), f3.u2, a1[0]);
            a2[0] = ffma2(pack2(m3.z), f3.u2, a2[0]);
        }
        for (; k < e; ++k) {
            float4 m = ent[k];
            F2U f;
            f.f2 = *(const float2*)(fb + __float_as_int(m.w) * CK + lane * 2);
            a0[0] = ffma2(pack2(m.x), f.u2, a0[0]);
            a1[0] = ffma2(pack2(m.y), f.u2, a1[0]);
            a2[0] = ffma2(pack2(m.z), f.u2, a2[0]);
        }
    }

    float* Fb = g_F + (size_t)bi * GBINS * CK;
    if (V2 == 2) {
        F4U o0, o1, o2;
        o0.u2[0] = a0[0]; o0.u2[1] = a0[1];
        o1.u2[0] = a1[0]; o1.u2[1] = a1[1];
        o2.u2[0] = a2[0]; o2.u2[1] = a2[1];
        *(float4*)(Fb + (0 * 16 + col) * CK + lane * 4) = o0.f4;
        *(float4*)(Fb + (1 * 16 + col) * CK + lane * 4) = o1.f4;
        *(float4*)(Fb + (2 * 16 + col) * CK + lane * 4) = o2.f4;
    } else {
        F2U o0, o1, o2;
        o0.u2 = a0[0]; o1.u2 = a1[0]; o2.u2 = a2[0];
        *(float2*)(Fb + (0 * 16 + col) * CK + lane * 2) = o0.f2;
        *(float2*)(Fb + (1 * 16 + col) * CK + lane * 2) = o1.f2;
        *(float2*)(Fb + (2 * 16 + col) * CK + lane * 2) = o2.f2;
    }
}

// ---------------- stage 2a: split-K GEMM (partials only) ----------------
template <int OK, int TM, int ROWS, int CPT, int KS>
__global__ void __launch_bounds__((TM / ROWS) * (OK / CPT)) gemm_kernel(int KD, int wOff) {
    const int KB = 32;
    const int THREADS = (TM / ROWS) * (OK / CPT);
    const int NW4 = (KB * OK / 4 + THREADS - 1) / THREADS;
    const int NF4 = (TM * KB / 4 + THREADS - 1) / THREADS;
    __shared__ __align__(16) float Wt[KB * OK];
    __shared__ __align__(16) float Ft[TM * KB];
    int tid = threadIdx.x;
    int i0 = blockIdx.x * TM;
    int KC = KD / KS;
    int k0 = blockIdx.y * KC;
    int NCH = KC / KB;

    const float* Wsrc = g_Wbig + wOff + (size_t)k0 * OK;

    float4 wreg[NW4], freg[NF4];
    {
        const float4* src = (const float4*)Wsrc;
#pragma unroll
        for (int u = 0; u < NW4; ++u) {
            int x = tid + u * THREADS;
            if (x < KB * OK / 4) wreg[u] = src[x];
        }
#pragma unroll
        for (int u = 0; u < NF4; ++u) {
            int x = tid + u * THREADS;
            if (x < TM * KB / 4) {
                int row = x / (KB / 4), kc = x % (KB / 4);
                freg[u] = *(const float4*)(g_F + (size_t)(i0 + row) * KD + k0 + kc * 4);
            }
        }
    }

    int rg = tid / (OK / CPT);
    int cg = (tid % (OK / CPT)) * CPT;
    unsigned long long accp[ROWS][CPT / 2];
#pragma unroll
    for (int r = 0; r < ROWS; ++r)
#pragma unroll
        for (int c = 0; c < CPT / 2; ++c) accp[r][c] = 0ull;

    for (int ch = 0; ch < NCH; ++ch) {
        __syncthreads();
#pragma unroll
        for (int u = 0; u < NW4; ++u) {
            int x = tid + u * THREADS;
            if (x < KB * OK / 4) ((float4*)Wt)[x] = wreg[u];
        }
#pragma unroll
        for (int u = 0; u < NF4; ++u) {
            int x = tid + u * THREADS;
            if (x < TM * KB / 4) ((float4*)Ft)[x] = freg[u];
        }
        __syncthreads();
        if (ch + 1 < NCH) {
            const float4* src = (const float4*)(Wsrc + (size_t)(ch + 1) * KB * OK);
#pragma unroll
            for (int u = 0; u < NW4; ++u) {
                int x = tid + u * THREADS;
                if (x < KB * OK / 4) wreg[u] = src[x];
            }
#pragma unroll
            for (int u = 0; u < NF4; ++u) {
                int x = tid + u * THREADS;
                if (x < TM * KB / 4) {
                    int rr = x / (KB / 4), kc = x % (KB / 4);
                    freg[u] = *(const float4*)(g_F + (size_t)(i0 + rr) * KD + k0 + (ch + 1) * KB + kc * 4);
                }
            }
        }
#pragma unroll 4
        for (int k = 0; k < KB; ++k) {
            unsigned long long fp[ROWS];
#pragma unroll
            for (int r = 0; r < ROWS; ++r)
                fp[r] = pack2(Ft[(rg * ROWS + r) * KB + k]);
#pragma unroll
            for (int c = 0; c < CPT; c += 4) {
                F4U w;
                w.f4 = *(const float4*)&Wt[k * OK + cg + c];
#pragma unroll
                for (int r = 0; r < ROWS; ++r) {
                    accp[r][c / 2]     = ffma2(fp[r], w.u2[0], accp[r][c / 2]);
                    accp[r][c / 2 + 1] = ffma2(fp[r], w.u2[1], accp[r][c / 2 + 1]);
                }
            }
        }
    }

#pragma unroll
    for (int r = 0; r < ROWS; ++r) {
        float* dst = g_part + ((size_t)blockIdx.y * BN + i0 + rg * ROWS + r) * OK + cg;
#pragma unroll
        for (int c = 0; c < CPT; c += 4) {
            F4U o;
            o.u2[0] = accp[r][c / 2];
            o.u2[1] = accp[r][c / 2 + 1];
            *(float4*)&dst[c] = o.f4;
        }
    }
}

// ---------------- stage 2b: 4-way split-parallel reduce + dense + epilogue ----------------
template <int OK, int KS, int CK>
__global__ void __launch_bounds__(256) reduce_kernel(int mode, int dOff,
                                                     int ain, int aout) {
    int tid = threadIdx.x;
    int warp = tid >> 5, lane = tid & 31;
    int s = lane & 3;
    int gidx = blockIdx.x * 64 + warp * 8 + (lane >> 2);
    int bi = gidx / OK, om = gidx % OK;

    float oc = 0.f;
#pragma unroll
    for (int ks = s; ks < KS; ks += 4)
        oc += g_part[((size_t)ks * BN + bi) * OK + om];

    const float* __restrict__ densein = (ain == 0) ? g_regD : (ain == 1) ? g_actA : g_actB;
    float* __restrict__ actout = (aout == 1) ? g_actA : g_actB;
    const float* WdT = g_WdT + dOff;
    const float* x = densein + (size_t)bi * CK;
    float od = 0.f;
    const int CPT = CK / 4;
#pragma unroll
    for (int u = 0; u < CPT; ++u) {
        int cn = s * CPT + u;
        od = fmaf(x[cn], WdT[cn * OK + om], od);
    }
    oc += __shfl_xor_sync(0xffffffffu, oc, 1);
    oc += __shfl_xor_sync(0xffffffffu, oc, 2);
    od += __shfl_xor_sync(0xffffffffu, od, 1);
    od += __shfl_xor_sync(0xffffffffu, od, 2);

    if (mode == 0) {
        float sc = oc * oc;
        sc += __shfl_xor_sync(0xffffffffu, sc, 4);
        sc += __shfl_xor_sync(0xffffffffu, sc, 8);
        sc += __shfl_xor_sync(0xffffffffu, sc, 16);
        float mc = sc + 1e-6f;
        float sd = od * od;
        sd += __shfl_xor_sync(0xffffffffu, sd, 4);
        sd += __shfl_xor_sync(0xffffffffu, sd, 8);
        sd += __shfl_xor_sync(0xffffffffu, sd, 16);
        float md = sd + 1e-6f;
        if (s == 0) {
            g_out[bi * 64 + om] = oc;
            g_out[bi * 64 + 32 + om] = od;
            actout[bi * 64 + om] = oc / mc * fmaxf(mc - 0.2f, 0.f);
            actout[bi * 64 + 32 + om] = od / md * fmaxf(md - 0.2f, 0.f);
        }
    } else {
        float v = oc + od;
        if (mode == 2) v += g_out[bi * OK + om];
        float sq = v * v;
        sq += __shfl_xor_sync(0xffffffffu, sq, 4);
        sq += __shfl_xor_sync(0xffffffffu, sq, 8);
        sq += __shfl_xor_sync(0xffffffffu, sq, 16);
        float mg = sq + 1e-6f;
        if (s == 0) {
            g_out[bi * OK + om] = v;
            actout[bi * OK + om] = v / mg * fmaxf(mg - 0.2f, 0.f);
        }
    }
}

// ---------------- last layer: split-parallel reduce + dense + projection ----------------
__global__ void __launch_bounds__(256) reduce_last(const float* __restrict__ p0,
                                                   const float* __restrict__ pc,
                                                   const float* __restrict__ pd,
                                                   float* __restrict__ outp) {
    const int OK = 24, KS = 8, CK = 64;
    int tid = threadIdx.x;
    int warp = tid >> 5, lane = tid & 31;
    int s = lane & 3;
    int gidx = blockIdx.x * 64 + warp * 8 + (lane >> 2);
    int bi = gidx / OK, om = gidx % OK;
    int m = om & 7, ch = om >> 3;

    float oc = 0.f;
#pragma unroll
    for (int ks = s; ks < KS; ks += 4)
        oc += g_part[((size_t)ks * BN + bi) * OK + om];

    const float* WdT = g_WdT + 24576;
    const float* x = g_actB + (size_t)bi * CK;
    float od = 0.f;
#pragma unroll
    for (int u = 0; u < 16; ++u) {
        int cn = s * 16 + u;
        od = fmaf(x[cn], WdT[cn * OK + om], od);
    }
    oc += __shfl_xor_sync(0xffffffffu, oc, 1);
    oc += __shfl_xor_sync(0xffffffffu, oc, 2);
    od += __shfl_xor_sync(0xffffffffu, od, 1);
    od += __shfl_xor_sync(0xffffffffu, od, 2);

    float th = (float)m * 0.78539816339744831f;
    float cs = cosf(th), sn = sinf(th);
    float c0 = pc[0], c1 = pc[1], d0 = pd[0], d1 = pd[1];
    float resx = oc * (c0 * cs - c1 * sn) + od * (d0 * cs - d1 * sn);
    float resy = oc * (c0 * sn + c1 * cs) + od * (d0 * sn + d1 * cs);
    resx += __shfl_xor_sync(0xffffffffu, resx, 4);
    resx += __shfl_xor_sync(0xffffffffu, resx, 8);
    resx += __shfl_xor_sync(0xffffffffu, resx, 16);
    resy += __shfl_xor_sync(0xffffffffu, resy, 4);
    resy += __shfl_xor_sync(0xffffffffu, resy, 8);
    resy += __shfl_xor_sync(0xffffffffu, resy, 16);

    if (lane == 0) {
        const float CORR = 1.0f / 128.0f;
        resx *= CORR;
        resy *= CORR;
        if (ch == 0) {
            float px = g_p1[bi * 2 + 0] + resx;
            float py = g_p1[bi * 2 + 1] + resy;
            outp[bi * 2 + 0] = px;
            outp[bi * 2 + 1] = py;
            outp[BN * 2 + bi * 2 + 0] = px - p0[bi * 2 + 0];
            outp[BN * 2 + bi * 2 + 1] = py - p0[bi * 2 + 1];
        } else {
            outp[BN * 4 + bi * 4 + (ch - 1) * 2 + 0] = resx;
            outp[BN * 4 + bi * 4 + (ch - 1) * 2 + 1] = resy;
        }
    }
}

// ---------------- launch ----------------
extern "C" void kernel_launch(void* const* d_in, const int* in_sizes, int n_in,
                              void* d_out, int out_size) {
    const float* p0_enc  = (const float*)d_in[0];
    const float* v0_enc  = (const float*)d_in[1];
    const float* p0      = (const float*)d_in[2];
    const float* v0      = (const float*)d_in[3];
    const float* a       = (const float*)d_in[4];
    const float* mask    = (const float*)d_in[5];
    const float* lift_c0 = (const float*)d_in[6];
    const float* Wc0     = (const float*)d_in[7];
    const float* lift_d0 = (const float*)d_in[8];
    const float* Wd0     = (const float*)d_in[9];
    const float* Wc1     = (const float*)d_in[10];
    const float* Wd1     = (const float*)d_in[11];
    const float* Wc2     = (const float*)d_in[12];
    const float* Wd2     = (const float*)d_in[13];
    const float* Wc3     = (const float*)d_in[14];
    const float* Wd3     = (const float*)d_in[15];
    const float* Wc4     = (const float*)d_in[16];
    const float* proj_c4 = (const float*)d_in[17];
    const float* Wd4     = (const float*)d_in[18];
    const float* proj_d4 = (const float*)d_in[19];

    const int NEXP = (1253376 + 26112 + 255) / 256;
    prep_kernel<<<BN + NEXP, 256>>>(mask, p0, v0, a, p0_enc, v0_enc,
                                    lift_c0, lift_d0,
                                    Wc0, Wc1, Wc2, Wc3, Wc4,
                                    Wd0, Wd1, Wd2, Wd3, Wd4);

    const int wOff[5] = {0, 196608, 393216, 786432, 1179648};
    const int dOff[5] = {0, 4096, 8192, 16384, 24576};

    // act ping-pong: L0 -> A; L1: A->B; L2: B->A; L3: A->B; L4: reads B
    // L0: CK=128, OK=32, KD=6144
    stage1_kernel<128><<<BN * 2, 256>>>(0);
    gemm_kernel<32, 128, 2, 8, 16><<<dim3(8, 16), 256>>>(6144, wOff[0]);
    reduce_kernel<32, 16, 128><<<BN * 32 / 64, 256>>>(0, dOff[0], 0, 1);
    // L1: CK=64, OK=64, KD=3072, residual
    stage1_kernel<64><<<BN * 2, 256>>>(1);
    gemm_kernel<64, 64, 2, 8, 16><<<dim3(16, 16), 256>>>(3072, wOff[1]);
    reduce_kernel<64, 16, 64><<<BN * 64 / 64, 256>>>(2, dOff[1], 1, 2);
    // L2: CK=64, OK=128, KD=3072
    stage1_kernel<64><<<BN * 2, 256>>>(2);
    gemm_kernel<128, 32, 2, 8, 8><<<dim3(32, 8), 256>>>(3072, wOff[2]);
    reduce_kernel<128, 8, 64><<<BN * 128 / 64, 256>>>(1, dOff[2], 2, 1);
    // L3: CK=128, OK=64, KD=6144
    stage1_kernel<128><<<BN * 2, 256>>>(1);
    gemm_kernel<64, 64, 2, 8, 16><<<dim3(16, 16), 256>>>(6144, wOff[3]);
    reduce_kernel<64, 16, 128><<<BN * 64 / 64, 256>>>(1, dOff[3], 1, 2);
    // L4: CK=64, OK=24, KD=3072, last (fused projection)
    stage1_kernel<64><<<BN * 2, 256>>>(2);
    gemm_kernel<24, 128, 2, 8, 8><<<dim3(8, 8), 192>>>(3072, wOff[4]);
    reduce_last<<<BN * 24 / 64, 256>>>(p0, proj_c4, proj_d4, (float*)d_out);
}